// round 2
// baseline (speedup 1.0000x reference)
#include <cuda_runtime.h>
#include <cuda_bf16.h>
#include <math.h>

// Problem constants
#define B_  2
#define S_  2048
#define HID_ 2048
#define H_  16
#define KV_ 8
#define D_  128
#define SCALE_ 0.08838834764831845f  // 1/sqrt(128)
#define EPS_ 1e-6f

// ---------------- scratch (device globals; no allocations allowed) ----------
__device__ float g_q[(size_t)B_ * S_ * H_ * D_];    // [B*S, H*D]  33.5 MB
__device__ float g_k[(size_t)B_ * S_ * KV_ * D_];   // [B*S, KV*D] 16.8 MB
__device__ float g_v[(size_t)B_ * S_ * KV_ * D_];   // 16.8 MB
__device__ float g_o[(size_t)B_ * S_ * H_ * D_];    // attn out [B*S, H*D]

// ---------------- SGEMM: C[M,N] = A[M,K] @ B[K,N], all row-major ------------
#define BM 128
#define BN 128
#define BKK 16

__global__ __launch_bounds__(256) void sgemm_kernel(
    const float* __restrict__ A, const float* __restrict__ Bm,
    float* __restrict__ C, int M, int N, int K)
{
    __shared__ float As[BKK][BM];
    __shared__ float Bs[BKK][BN];

    const int tid = threadIdx.x;
    const int bx = blockIdx.x, by = blockIdx.y;
    const int tx = tid & 15;       // 0..15 (cols)
    const int ty = tid >> 4;       // 0..15 (rows)

    float acc[8][8];
    #pragma unroll
    for (int i = 0; i < 8; i++)
        #pragma unroll
        for (int j = 0; j < 8; j++) acc[i][j] = 0.0f;

    const float* Ab = A + (size_t)by * BM * K;
    const float* Bb = Bm + (size_t)bx * BN;

    for (int k0 = 0; k0 < K; k0 += BKK) {
        // Load A tile 128x16 (512 float4, 2 per thread), store transposed
        #pragma unroll
        for (int i = 0; i < 2; i++) {
            int idx = tid + i * 256;
            int row = idx >> 2;
            int c4  = (idx & 3) * 4;
            float4 v = *(const float4*)(Ab + (size_t)row * K + k0 + c4);
            As[c4 + 0][row] = v.x;
            As[c4 + 1][row] = v.y;
            As[c4 + 2][row] = v.z;
            As[c4 + 3][row] = v.w;
        }
        // Load B tile 16x128
        #pragma unroll
        for (int i = 0; i < 2; i++) {
            int idx = tid + i * 256;
            int row = idx >> 5;
            int c4  = (idx & 31) * 4;
            *(float4*)(&Bs[row][c4]) =
                *(const float4*)(Bb + (size_t)(k0 + row) * N + c4);
        }
        __syncthreads();

        #pragma unroll
        for (int k = 0; k < BKK; k++) {
            float a[8], b[8];
            #pragma unroll
            for (int i = 0; i < 8; i++) a[i] = As[k][ty * 8 + i];
            #pragma unroll
            for (int i = 0; i < 8; i++) b[i] = Bs[k][tx * 8 + i];
            #pragma unroll
            for (int i = 0; i < 8; i++)
                #pragma unroll
                for (int j = 0; j < 8; j++)
                    acc[i][j] += a[i] * b[j];
        }
        __syncthreads();
    }

    #pragma unroll
    for (int i = 0; i < 8; i++) {
        size_t row = (size_t)by * BM + ty * 8 + i;
        float* Crow = C + row * N + (size_t)bx * BN + tx * 8;
        *(float4*)(Crow)     = make_float4(acc[i][0], acc[i][1], acc[i][2], acc[i][3]);
        *(float4*)(Crow + 4) = make_float4(acc[i][4], acc[i][5], acc[i][6], acc[i][7]);
    }
}

// ---------------- fused per-head RMSNorm + RoPE (in-place) ------------------
// one 128-thread block per (b*s, head) row of D=128
__global__ __launch_bounds__(128) void norm_rope_kernel(
    float* __restrict__ buf, const float* __restrict__ w,
    const float* __restrict__ cosb, const float* __restrict__ sinb, int nheads)
{
    const int blk  = blockIdx.x;
    const int head = blk % nheads;
    const int bs   = blk / nheads;           // 0..B*S-1
    const int s    = bs % S_;
    float* row = buf + ((size_t)bs * nheads + head) * D_;
    const int d = threadIdx.x;

    float v = row[d];
    float ss = v * v;
    #pragma unroll
    for (int o = 16; o > 0; o >>= 1) ss += __shfl_xor_sync(0xffffffffu, ss, o);

    __shared__ float warp_ss[4];
    __shared__ float sh[D_];
    if ((d & 31) == 0) warp_ss[d >> 5] = ss;
    __syncthreads();
    float total = warp_ss[0] + warp_ss[1] + warp_ss[2] + warp_ss[3];
    float r = rsqrtf(total * (1.0f / (float)D_) + EPS_);
    float xn = v * r * w[d];
    sh[d] = xn;
    __syncthreads();
    float rot = (d < 64) ? -sh[d + 64] : sh[d - 64];
    row[d] = xn * cosb[s * D_ + d] + rot * sinb[s * D_ + d];
}

// ---------------- causal GQA flash attention (fp32) -------------------------
// grid: (32 qblocks, H, B); 128 threads; BQ=64, BK=64, D=128
#define BQ 64
#define BKT 64
#define QSTR 132   // padded row stride for Q/K/V tiles
#define PSTR 68    // padded row stride for P tile

__global__ __launch_bounds__(128) void flash_kernel(
    const float* __restrict__ q, const float* __restrict__ k,
    const float* __restrict__ v, float* __restrict__ o)
{
    extern __shared__ float sm[];
    float* sQ = sm;                       // 64*132
    float* sK = sQ + BQ * QSTR;           // 64*132
    float* sV = sK + BKT * QSTR;          // 64*132
    float* sP = sV + BKT * QSTR;          // 64*68

    const int qb = blockIdx.x;            // 0..31
    const int h  = blockIdx.y;            // 0..15
    const int b  = blockIdx.z;            // 0..1
    const int g  = h >> 1;                // kv head
    const int tid = threadIdx.x;
    const int tx = tid & 7;               // 0..7
    const int ty = tid >> 3;              // 0..15
    const int q0 = qb * BQ;

    // Load Q tile [64][128]
    for (int i = tid; i < BQ * 32; i += 128) {
        int row = i >> 5;
        int c4  = (i & 31) * 4;
        *(float4*)(sQ + row * QSTR + c4) =
            *(const float4*)(q + (((size_t)(b * S_ + q0 + row) * H_ + h) * D_) + c4);
    }

    float acc[4][16];
    #pragma unroll
    for (int r = 0; r < 4; r++)
        #pragma unroll
        for (int c = 0; c < 16; c++) acc[r][c] = 0.0f;
    float mrow[4] = {-1e30f, -1e30f, -1e30f, -1e30f};
    float lrow[4] = {0.0f, 0.0f, 0.0f, 0.0f};

    for (int j = 0; j <= qb; j++) {
        const int k0 = j * BKT;
        __syncthreads();  // previous PV must finish before overwriting K/V
        for (int i = tid; i < BKT * 32; i += 128) {
            int row = i >> 5;
            int c4  = (i & 31) * 4;
            size_t base = (((size_t)(b * S_ + k0 + row) * KV_ + g) * D_) + c4;
            *(float4*)(sK + row * QSTR + c4) = *(const float4*)(k + base);
            *(float4*)(sV + row * QSTR + c4) = *(const float4*)(v + base);
        }
        __syncthreads();

        // S = Q K^T  (micro-tile 4x8 per thread)
        float s[4][8];
        #pragma unroll
        for (int r = 0; r < 4; r++)
            #pragma unroll
            for (int c = 0; c < 8; c++) s[r][c] = 0.0f;

        for (int d4 = 0; d4 < 32; d4++) {
            float4 qa[4], kb[8];
            #pragma unroll
            for (int r = 0; r < 4; r++)
                qa[r] = *(float4*)(sQ + (ty * 4 + r) * QSTR + d4 * 4);
            #pragma unroll
            for (int c = 0; c < 8; c++)
                kb[c] = *(float4*)(sK + (tx * 8 + c) * QSTR + d4 * 4);
            #pragma unroll
            for (int r = 0; r < 4; r++)
                #pragma unroll
                for (int c = 0; c < 8; c++)
                    s[r][c] += qa[r].x * kb[c].x + qa[r].y * kb[c].y +
                               qa[r].z * kb[c].z + qa[r].w * kb[c].w;
        }

        // scale + causal mask
        #pragma unroll
        for (int r = 0; r < 4; r++) {
            int qg = q0 + ty * 4 + r;
            #pragma unroll
            for (int c = 0; c < 8; c++) {
                int kg = k0 + tx * 8 + c;
                s[r][c] = (kg <= qg) ? s[r][c] * SCALE_ : -1e30f;
            }
        }

        // streaming softmax update (row groups of 8 lanes share ty)
        #pragma unroll
        for (int r = 0; r < 4; r++) {
            float mx = s[r][0];
            #pragma unroll
            for (int c = 1; c < 8; c++) mx = fmaxf(mx, s[r][c]);
            #pragma unroll
            for (int o2 = 1; o2 < 8; o2 <<= 1)
                mx = fmaxf(mx, __shfl_xor_sync(0xffffffffu, mx, o2));
            float mnew = fmaxf(mrow[r], mx);
            float alpha = __expf(mrow[r] - mnew);
            float ls = 0.0f;
            #pragma unroll
            for (int c = 0; c < 8; c++) {
                float p = __expf(s[r][c] - mnew);
                s[r][c] = p;
                ls += p;
            }
            #pragma unroll
            for (int o2 = 1; o2 < 8; o2 <<= 1)
                ls += __shfl_xor_sync(0xffffffffu, ls, o2);
            lrow[r] = lrow[r] * alpha + ls;
            mrow[r] = mnew;
            #pragma unroll
            for (int c = 0; c < 16; c++) acc[r][c] *= alpha;
            #pragma unroll
            for (int c = 0; c < 8; c++)
                sP[(ty * 4 + r) * PSTR + tx * 8 + c] = s[r][c];
        }
        __syncthreads();

        // O += P V  (rows ty*4..+3, cols tx*16..+15)
        for (int kk = 0; kk < BKT; kk++) {
            float pr[4];
            #pragma unroll
            for (int r = 0; r < 4; r++) pr[r] = sP[(ty * 4 + r) * PSTR + kk];
            float4 vv[4];
            #pragma unroll
            for (int c4 = 0; c4 < 4; c4++)
                vv[c4] = *(float4*)(sV + kk * QSTR + tx * 16 + c4 * 4);
            #pragma unroll
            for (int r = 0; r < 4; r++) {
                #pragma unroll
                for (int c4 = 0; c4 < 4; c4++) {
                    acc[r][c4 * 4 + 0] += pr[r] * vv[c4].x;
                    acc[r][c4 * 4 + 1] += pr[r] * vv[c4].y;
                    acc[r][c4 * 4 + 2] += pr[r] * vv[c4].z;
                    acc[r][c4 * 4 + 3] += pr[r] * vv[c4].w;
                }
            }
        }
    }

    // normalize and write
    #pragma unroll
    for (int r = 0; r < 4; r++) {
        float inv = 1.0f / lrow[r];
        int qg = q0 + ty * 4 + r;
        float* orow = o + (((size_t)(b * S_ + qg) * H_ + h) * D_) + tx * 16;
        #pragma unroll
        for (int c4 = 0; c4 < 4; c4++) {
            float4 w4 = make_float4(acc[r][c4 * 4 + 0] * inv, acc[r][c4 * 4 + 1] * inv,
                                    acc[r][c4 * 4 + 2] * inv, acc[r][c4 * 4 + 3] * inv);
            *(float4*)(orow + c4 * 4) = w4;
        }
    }
}

// ---------------- launch -----------------------------------------------------
extern "C" void kernel_launch(void* const* d_in, const int* in_sizes, int n_in,
                              void* d_out, int out_size)
{
    const float* x    = (const float*)d_in[0];
    const float* Wq   = (const float*)d_in[1];
    const float* Wk   = (const float*)d_in[2];
    const float* Wv   = (const float*)d_in[3];
    const float* Wo   = (const float*)d_in[4];
    const float* qw   = (const float*)d_in[5];
    const float* kw   = (const float*)d_in[6];
    const float* cosb = (const float*)d_in[7];
    const float* sinb = (const float*)d_in[8];

    float *qb, *kb, *vb, *ob;
    cudaGetSymbolAddress((void**)&qb, g_q);
    cudaGetSymbolAddress((void**)&kb, g_k);
    cudaGetSymbolAddress((void**)&vb, g_v);
    cudaGetSymbolAddress((void**)&ob, g_o);

    const int M = B_ * S_;  // 4096

    // QKV projections
    sgemm_kernel<<<dim3((H_ * D_) / BN, M / BM), 256>>>(x, Wq, qb, M, H_ * D_, HID_);
    sgemm_kernel<<<dim3((KV_ * D_) / BN, M / BM), 256>>>(x, Wk, kb, M, KV_ * D_, HID_);
    sgemm_kernel<<<dim3((KV_ * D_) / BN, M / BM), 256>>>(x, Wv, vb, M, KV_ * D_, HID_);

    // RMSNorm + RoPE (in place)
    norm_rope_kernel<<<B_ * S_ * H_, 128>>>(qb, qw, cosb, sinb, H_);
    norm_rope_kernel<<<B_ * S_ * KV_, 128>>>(kb, kw, cosb, sinb, KV_);

    // causal GQA flash attention
    const int smem = (3 * BQ * QSTR + BQ * PSTR) * (int)sizeof(float);  // 118784
    cudaFuncSetAttribute(flash_kernel, cudaFuncAttributeMaxDynamicSharedMemorySize, smem);
    flash_kernel<<<dim3(S_ / BQ, H_, B_), 128, smem>>>(qb, kb, vb, ob);

    // output projection -> d_out
    sgemm_kernel<<<dim3(HID_ / BN, M / BM), 256>>>(ob, Wo, (float*)d_out, M, HID_, HID_);
}

// round 4
// speedup vs baseline: 3.8164x; 3.8164x over previous
#include <cuda_runtime.h>
#include <cuda_bf16.h>
#include <math.h>

// Problem constants
#define B_  2
#define S_  2048
#define HID_ 2048
#define H_  16
#define KV_ 8
#define D_  128
#define SCALE_ 0.08838834764831845f  // 1/sqrt(128)
#define EPS_ 1e-6f

// ---------------- scratch (device globals; no allocations allowed) ----------
__device__ float g_q[(size_t)B_ * S_ * H_ * D_];
__device__ float g_k[(size_t)B_ * S_ * KV_ * D_];
__device__ float g_v[(size_t)B_ * S_ * KV_ * D_];
__device__ float g_o[(size_t)B_ * S_ * H_ * D_];

// ---------------- helpers ----------------------------------------------------
__device__ __forceinline__ float tf32r(float x) {
    unsigned u;
    asm("cvt.rna.tf32.f32 %0, %1;" : "=r"(u) : "f"(x));
    return __uint_as_float(u);
}
__device__ __forceinline__ unsigned fu(float x) { return __float_as_uint(x); }

__device__ __forceinline__ void mma8(float* c, const unsigned* a, unsigned b0, unsigned b1) {
    asm volatile(
        "mma.sync.aligned.m16n8k8.row.col.f32.tf32.tf32.f32 "
        "{%0,%1,%2,%3}, {%4,%5,%6,%7}, {%8,%9}, {%0,%1,%2,%3};\n"
        : "+f"(c[0]), "+f"(c[1]), "+f"(c[2]), "+f"(c[3])
        : "r"(a[0]), "r"(a[1]), "r"(a[2]), "r"(a[3]), "r"(b0), "r"(b1));
}

// ---------------- tf32 tensor-core GEMM: C = A[M,K] @ B[K,N], row-major ------
#define GBM 128
#define GBN 128
#define GBK 32
#define ASTR 36
#define BSTR 132

__global__ __launch_bounds__(256) void tf32_gemm(
    const float* __restrict__ A, const float* __restrict__ Bm,
    float* __restrict__ C, int M, int N, int K)
{
    __shared__ float As[GBM * ASTR];   // [row][k], stride 36
    __shared__ float Bs[GBK * BSTR];   // [k][col], stride 132

    const int tid  = threadIdx.x;
    const int lane = tid & 31;
    const int warp = tid >> 5;
    const int gq   = lane >> 2;
    const int tig  = lane & 3;
    const int wm   = warp >> 1;   // 0..3
    const int wn   = warp & 1;    // 0..1

    const float* Ab = A + (size_t)blockIdx.y * GBM * K;
    const float* Bb = Bm + (size_t)blockIdx.x * GBN;

    float c[2][8][4];
    #pragma unroll
    for (int mt = 0; mt < 2; mt++)
        #pragma unroll
        for (int nt = 0; nt < 8; nt++)
            #pragma unroll
            for (int i = 0; i < 4; i++) c[mt][nt][i] = 0.0f;

    for (int k0 = 0; k0 < K; k0 += GBK) {
        // A tile: 128x32 (1024 float4)
        #pragma unroll
        for (int it = 0; it < 4; it++) {
            int i   = tid + it * 256;
            int row = i >> 3;
            int cc  = (i & 7) << 2;
            float4 v = *(const float4*)(Ab + (size_t)row * K + (k0 + cc));
            float* p = As + row * ASTR + cc;
            p[0] = tf32r(v.x); p[1] = tf32r(v.y); p[2] = tf32r(v.z); p[3] = tf32r(v.w);
        }
        // B tile: 32x128
        #pragma unroll
        for (int it = 0; it < 4; it++) {
            int i   = tid + it * 256;
            int row = i >> 5;
            int cc  = (i & 31) << 2;
            float4 v = *(const float4*)(Bb + (size_t)(k0 + row) * N + cc);
            float* p = Bs + row * BSTR + cc;
            p[0] = tf32r(v.x); p[1] = tf32r(v.y); p[2] = tf32r(v.z); p[3] = tf32r(v.w);
        }
        __syncthreads();

        #pragma unroll
        for (int kk = 0; kk < GBK; kk += 8) {
            unsigned a[2][4];
            #pragma unroll
            for (int mt = 0; mt < 2; mt++) {
                const float* qp = As + (wm * 32 + mt * 16 + gq) * ASTR + kk + tig;
                a[mt][0] = fu(qp[0]);
                a[mt][1] = fu(qp[8 * ASTR]);
                a[mt][2] = fu(qp[4]);
                a[mt][3] = fu(qp[8 * ASTR + 4]);
            }
            #pragma unroll
            for (int nt = 0; nt < 8; nt++) {
                int col = wn * 64 + nt * 8 + gq;
                unsigned b0 = fu(Bs[(kk + tig)     * BSTR + col]);
                unsigned b1 = fu(Bs[(kk + tig + 4) * BSTR + col]);
                mma8(c[0][nt], a[0], b0, b1);
                mma8(c[1][nt], a[1], b0, b1);
            }
        }
        __syncthreads();
    }

    #pragma unroll
    for (int mt = 0; mt < 2; mt++) {
        int row0 = blockIdx.y * GBM + wm * 32 + mt * 16 + gq;
        #pragma unroll
        for (int nt = 0; nt < 8; nt++) {
            int col = blockIdx.x * GBN + wn * 64 + nt * 8 + 2 * tig;
            *(float2*)(C + (size_t)row0 * N + col)       = make_float2(c[mt][nt][0], c[mt][nt][1]);
            *(float2*)(C + (size_t)(row0 + 8) * N + col) = make_float2(c[mt][nt][2], c[mt][nt][3]);
        }
    }
}

// ---------------- fused per-head RMSNorm + RoPE (in-place) ------------------
__global__ __launch_bounds__(128) void norm_rope_kernel(
    float* __restrict__ buf, const float* __restrict__ w,
    const float* __restrict__ cosb, const float* __restrict__ sinb, int nheads)
{
    const int blk  = blockIdx.x;
    const int head = blk % nheads;
    const int bs   = blk / nheads;
    const int s    = bs % S_;
    float* row = buf + ((size_t)bs * nheads + head) * D_;
    const int d = threadIdx.x;

    float v = row[d];
    float ss = v * v;
    #pragma unroll
    for (int o = 16; o > 0; o >>= 1) ss += __shfl_xor_sync(0xffffffffu, ss, o);

    __shared__ float warp_ss[4];
    __shared__ float sh[D_];
    if ((d & 31) == 0) warp_ss[d >> 5] = ss;
    __syncthreads();
    float total = warp_ss[0] + warp_ss[1] + warp_ss[2] + warp_ss[3];
    float r = rsqrtf(total * (1.0f / (float)D_) + EPS_);
    float xn = v * r * w[d];
    sh[d] = xn;
    __syncthreads();
    float rot = (d < 64) ? -sh[d + 64] : sh[d - 64];
    row[d] = xn * cosb[s * D_ + d] + rot * sinb[s * D_ + d];
}

// ---------------- causal GQA flash attention (tf32 tensor cores) -------------
// grid: (32 qblocks, H, B); 128 threads (4 warps); BQ=64, BK=64, D=128
// warp w owns query rows [w*16, w*16+16)
#define BQ 64
#define BKT 64
#define QSTR 132
#define PSTR 68

__global__ __launch_bounds__(128) void flash_tc(
    const float* __restrict__ q, const float* __restrict__ k,
    const float* __restrict__ v, float* __restrict__ o)
{
    extern __shared__ float sm[];
    float* sQ = sm;                       // 64*132
    float* sK = sQ + BQ * QSTR;           // 64*132
    float* sV = sK + BKT * QSTR;          // 64*132
    float* sP = sV + BKT * QSTR;          // 64*68

    const int qb  = blockIdx.x;
    const int h   = blockIdx.y;
    const int b   = blockIdx.z;
    const int kvh = h >> 1;
    const int tid  = threadIdx.x;
    const int lane = tid & 31;
    const int warp = tid >> 5;
    const int gq   = lane >> 2;
    const int tig  = lane & 3;
    const int q0   = qb * BQ;

    // Load + tf32-round Q tile [64][128]
    for (int i = tid; i < BQ * 32; i += 128) {
        int row = i >> 5;
        int cc  = (i & 31) << 2;
        float4 val = *(const float4*)(q + (((size_t)(b * S_ + q0 + row) * H_ + h) * D_) + cc);
        float* p = sQ + row * QSTR + cc;
        p[0] = tf32r(val.x); p[1] = tf32r(val.y); p[2] = tf32r(val.z); p[3] = tf32r(val.w);
    }

    float oc[16][4];
    #pragma unroll
    for (int nt = 0; nt < 16; nt++)
        #pragma unroll
        for (int i = 0; i < 4; i++) oc[nt][i] = 0.0f;
    float mrow0 = -1e30f, mrow1 = -1e30f;
    float lrow0 = 0.0f,   lrow1 = 0.0f;

    const int r0 = q0 + warp * 16 + gq;   // row for c0/c1
    const int r1 = r0 + 8;                // row for c2/c3

    for (int j = 0; j <= qb; j++) {
        const int kt0 = j * BKT;
        __syncthreads();  // prior PV reads of sV done before overwrite
        for (int i = tid; i < BKT * 32; i += 128) {
            int row = i >> 5;
            int cc  = (i & 31) << 2;
            size_t base = (((size_t)(b * S_ + kt0 + row) * KV_ + kvh) * D_) + cc;
            float4 kv4 = *(const float4*)(k + base);
            float4 vv4 = *(const float4*)(v + base);
            float* pk = sK + row * QSTR + cc;
            pk[0] = tf32r(kv4.x); pk[1] = tf32r(kv4.y); pk[2] = tf32r(kv4.z); pk[3] = tf32r(kv4.w);
            float* pv = sV + row * QSTR + cc;
            pv[0] = tf32r(vv4.x); pv[1] = tf32r(vv4.y); pv[2] = tf32r(vv4.z); pv[3] = tf32r(vv4.w);
        }
        __syncthreads();

        // S = Q K^T : 8 n-tiles over 64 keys, k-loop over D
        float s[8][4];
        #pragma unroll
        for (int nt = 0; nt < 8; nt++)
            #pragma unroll
            for (int i = 0; i < 4; i++) s[nt][i] = 0.0f;

        #pragma unroll
        for (int kk = 0; kk < D_; kk += 8) {
            unsigned a[4];
            const float* qp = sQ + (warp * 16 + gq) * QSTR + kk + tig;
            a[0] = fu(qp[0]);
            a[1] = fu(qp[8 * QSTR]);
            a[2] = fu(qp[4]);
            a[3] = fu(qp[8 * QSTR + 4]);
            #pragma unroll
            for (int nt = 0; nt < 8; nt++) {
                const float* kp = sK + (nt * 8 + gq) * QSTR + kk + tig;
                unsigned b0 = fu(kp[0]);
                unsigned b1 = fu(kp[4]);
                mma8(s[nt], a, b0, b1);
            }
        }

        // scale + causal mask + row max (C layout: rows r0/r1, cols 2*tig, 2*tig+1)
        float mx0 = -1e30f, mx1 = -1e30f;
        #pragma unroll
        for (int nt = 0; nt < 8; nt++) {
            int kg = kt0 + nt * 8 + 2 * tig;
            s[nt][0] = (kg     <= r0) ? s[nt][0] * SCALE_ : -1e30f;
            s[nt][1] = (kg + 1 <= r0) ? s[nt][1] * SCALE_ : -1e30f;
            s[nt][2] = (kg     <= r1) ? s[nt][2] * SCALE_ : -1e30f;
            s[nt][3] = (kg + 1 <= r1) ? s[nt][3] * SCALE_ : -1e30f;
            mx0 = fmaxf(mx0, fmaxf(s[nt][0], s[nt][1]));
            mx1 = fmaxf(mx1, fmaxf(s[nt][2], s[nt][3]));
        }
        mx0 = fmaxf(mx0, __shfl_xor_sync(0xffffffffu, mx0, 1));
        mx0 = fmaxf(mx0, __shfl_xor_sync(0xffffffffu, mx0, 2));
        mx1 = fmaxf(mx1, __shfl_xor_sync(0xffffffffu, mx1, 1));
        mx1 = fmaxf(mx1, __shfl_xor_sync(0xffffffffu, mx1, 2));

        float mn0 = fmaxf(mrow0, mx0), mn1 = fmaxf(mrow1, mx1);
        float al0 = __expf(mrow0 - mn0), al1 = __expf(mrow1 - mn1);

        float ls0 = 0.0f, ls1 = 0.0f;
        float* pbase = sP + (warp * 16 + gq) * PSTR + 2 * tig;
        #pragma unroll
        for (int nt = 0; nt < 8; nt++) {
            float p0 = __expf(s[nt][0] - mn0);
            float p1 = __expf(s[nt][1] - mn0);
            float p2 = __expf(s[nt][2] - mn1);
            float p3 = __expf(s[nt][3] - mn1);
            ls0 += p0 + p1;
            ls1 += p2 + p3;
            pbase[nt * 8]                = tf32r(p0);
            pbase[nt * 8 + 1]            = tf32r(p1);
            pbase[nt * 8 + 8 * PSTR]     = tf32r(p2);
            pbase[nt * 8 + 8 * PSTR + 1] = tf32r(p3);
        }
        ls0 += __shfl_xor_sync(0xffffffffu, ls0, 1);
        ls0 += __shfl_xor_sync(0xffffffffu, ls0, 2);
        ls1 += __shfl_xor_sync(0xffffffffu, ls1, 1);
        ls1 += __shfl_xor_sync(0xffffffffu, ls1, 2);
        lrow0 = lrow0 * al0 + ls0;  mrow0 = mn0;
        lrow1 = lrow1 * al1 + ls1;  mrow1 = mn1;

        // rescale O accumulators
        #pragma unroll
        for (int nt = 0; nt < 16; nt++) {
            oc[nt][0] *= al0; oc[nt][1] *= al0;
            oc[nt][2] *= al1; oc[nt][3] *= al1;
        }
        __syncwarp();

        // O += P V : 16 n-tiles over D, k-loop over 64 keys
        #pragma unroll
        for (int kt = 0; kt < BKT; kt += 8) {
            unsigned a[4];
            const float* pp = sP + (warp * 16 + gq) * PSTR + kt + tig;
            a[0] = fu(pp[0]);
            a[1] = fu(pp[8 * PSTR]);
            a[2] = fu(pp[4]);
            a[3] = fu(pp[8 * PSTR + 4]);
            #pragma unroll
            for (int nt = 0; nt < 16; nt++) {
                const float* vp = sV + (kt + tig) * QSTR + nt * 8 + gq;
                unsigned b0 = fu(vp[0]);
                unsigned b1 = fu(vp[4 * QSTR]);
                mma8(oc[nt], a, b0, b1);
            }
        }
        __syncwarp();
    }

    // normalize + write
    float inv0 = 1.0f / lrow0, inv1 = 1.0f / lrow1;
    #pragma unroll
    for (int nt = 0; nt < 16; nt++) {
        int col = nt * 8 + 2 * tig;
        float* op0 = o + (((size_t)(b * S_ + r0) * H_ + h) * D_) + col;
        float* op1 = o + (((size_t)(b * S_ + r1) * H_ + h) * D_) + col;
        *(float2*)op0 = make_float2(oc[nt][0] * inv0, oc[nt][1] * inv0);
        *(float2*)op1 = make_float2(oc[nt][2] * inv1, oc[nt][3] * inv1);
    }
}

// ---------------- launch -----------------------------------------------------
extern "C" void kernel_launch(void* const* d_in, const int* in_sizes, int n_in,
                              void* d_out, int out_size)
{
    const float* x    = (const float*)d_in[0];
    const float* Wq   = (const float*)d_in[1];
    const float* Wk   = (const float*)d_in[2];
    const float* Wv   = (const float*)d_in[3];
    const float* Wo   = (const float*)d_in[4];
    const float* qw   = (const float*)d_in[5];
    const float* kw   = (const float*)d_in[6];
    const float* cosb = (const float*)d_in[7];
    const float* sinb = (const float*)d_in[8];

    float *qb, *kb, *vb, *ob;
    cudaGetSymbolAddress((void**)&qb, g_q);
    cudaGetSymbolAddress((void**)&kb, g_k);
    cudaGetSymbolAddress((void**)&vb, g_v);
    cudaGetSymbolAddress((void**)&ob, g_o);

    const int M = B_ * S_;  // 4096

    // QKV projections (tf32 tensor cores)
    tf32_gemm<<<dim3((H_ * D_) / GBN, M / GBM), 256>>>(x, Wq, qb, M, H_ * D_, HID_);
    tf32_gemm<<<dim3((KV_ * D_) / GBN, M / GBM), 256>>>(x, Wk, kb, M, KV_ * D_, HID_);
    tf32_gemm<<<dim3((KV_ * D_) / GBN, M / GBM), 256>>>(x, Wv, vb, M, KV_ * D_, HID_);

    // RMSNorm + RoPE (in place)
    norm_rope_kernel<<<B_ * S_ * H_, 128>>>(qb, qw, cosb, sinb, H_);
    norm_rope_kernel<<<B_ * S_ * KV_, 128>>>(kb, kw, cosb, sinb, KV_);

    // causal GQA flash attention (tf32 tensor cores)
    const int smem = (3 * BQ * QSTR + BQ * PSTR) * (int)sizeof(float);  // 118784
    cudaFuncSetAttribute(flash_tc, cudaFuncAttributeMaxDynamicSharedMemorySize, smem);
    flash_tc<<<dim3(S_ / BQ, H_, B_), 128, smem>>>(qb, kb, vb, ob);

    // output projection -> d_out
    tf32_gemm<<<dim3(HID_ / GBN, M / GBM), 256>>>(ob, Wo, (float*)d_out, M, HID_, HID_);
}

// round 5
// speedup vs baseline: 4.3811x; 1.1480x over previous
#include <cuda_runtime.h>
#include <cuda_bf16.h>
#include <math.h>

// Problem constants
#define B_  2
#define S_  2048
#define HID_ 2048
#define H_  16
#define KV_ 8
#define D_  128
#define SCALE_ 0.08838834764831845f  // 1/sqrt(128)
#define EPS_ 1e-6f

// ---------------- scratch (device globals; no allocations allowed) ----------
__device__ float g_q[(size_t)B_ * S_ * H_ * D_];
__device__ float g_k[(size_t)B_ * S_ * KV_ * D_];
__device__ float g_v[(size_t)B_ * S_ * KV_ * D_];
__device__ float g_o[(size_t)B_ * S_ * H_ * D_];
// pre-rounded (tf32) copies of GEMM inputs
__device__ float g_xr[(size_t)B_ * S_ * HID_];
__device__ float g_wqr[(size_t)HID_ * H_ * D_];
__device__ float g_wkr[(size_t)HID_ * KV_ * D_];
__device__ float g_wvr[(size_t)HID_ * KV_ * D_];
__device__ float g_wor[(size_t)H_ * D_ * HID_];

// ---------------- helpers ----------------------------------------------------
__device__ __forceinline__ float tf32r(float x) {
    unsigned u;
    asm("cvt.rna.tf32.f32 %0, %1;" : "=r"(u) : "f"(x));
    return __uint_as_float(u);
}
__device__ __forceinline__ unsigned fu(float x) { return __float_as_uint(x); }

__device__ __forceinline__ void mma8(float* c, const unsigned* a, unsigned b0, unsigned b1) {
    asm volatile(
        "mma.sync.aligned.m16n8k8.row.col.f32.tf32.tf32.f32 "
        "{%0,%1,%2,%3}, {%4,%5,%6,%7}, {%8,%9}, {%0,%1,%2,%3};\n"
        : "+f"(c[0]), "+f"(c[1]), "+f"(c[2]), "+f"(c[3])
        : "r"(a[0]), "r"(a[1]), "r"(a[2]), "r"(a[3]), "r"(b0), "r"(b1));
}

__device__ __forceinline__ void cp16(float* dst_smem, const float* src_gmem) {
    unsigned d = (unsigned)__cvta_generic_to_shared(dst_smem);
    asm volatile("cp.async.cg.shared.global [%0], [%1], 16;\n" :: "r"(d), "l"(src_gmem));
}
__device__ __forceinline__ void cp_commit() {
    asm volatile("cp.async.commit_group;\n");
}
__device__ __forceinline__ void cp_wait0() {
    asm volatile("cp.async.wait_group 0;\n");
}

// ---------------- tf32 round pass (elementwise, float4) ----------------------
__global__ __launch_bounds__(256) void round_tf32_kernel(
    const float* __restrict__ in, float* __restrict__ out, int n4)
{
    int i = blockIdx.x * blockDim.x + threadIdx.x;
    if (i < n4) {
        float4 v = ((const float4*)in)[i];
        v.x = tf32r(v.x); v.y = tf32r(v.y); v.z = tf32r(v.z); v.w = tf32r(v.w);
        ((float4*)out)[i] = v;
    }
}

// ---------------- cp.async double-buffered tf32 GEMM -------------------------
// C[M,N] = A[M,K] @ B[K,N]; A,B already tf32-rounded.
#define GBM 128
#define GBN 128
#define GBK 32
#define ASTR 36
#define BSTR 132

__global__ __launch_bounds__(256) void tf32_gemm_async(
    const float* __restrict__ A, const float* __restrict__ Bm,
    float* __restrict__ C, int M, int N, int K)
{
    __shared__ float As[2][GBM * ASTR];
    __shared__ float Bs[2][GBK * BSTR];

    const int tid  = threadIdx.x;
    const int lane = tid & 31;
    const int warp = tid >> 5;
    const int gq   = lane >> 2;
    const int tig  = lane & 3;
    const int wm   = warp >> 1;   // 0..3
    const int wn   = warp & 1;    // 0..1

    const float* Ab = A + (size_t)blockIdx.y * GBM * K;
    const float* Bb = Bm + (size_t)blockIdx.x * GBN;

    float c[2][8][4];
    #pragma unroll
    for (int mt = 0; mt < 2; mt++)
        #pragma unroll
        for (int nt = 0; nt < 8; nt++)
            #pragma unroll
            for (int i = 0; i < 4; i++) c[mt][nt][i] = 0.0f;

    const int T = K / GBK;

    // tile issue: A 128x32 = 1024 16B-chunks, B 32x128 = 1024 16B-chunks
    auto issue = [&](int t, int st) {
        int k0 = t * GBK;
        #pragma unroll
        for (int it = 0; it < 4; it++) {
            int ch  = tid + it * 256;
            int row = ch >> 3;
            int cc  = (ch & 7) << 2;
            cp16(&As[st][row * ASTR + cc], Ab + (size_t)row * K + k0 + cc);
        }
        #pragma unroll
        for (int it = 0; it < 4; it++) {
            int ch  = tid + it * 256;
            int row = ch >> 5;
            int cc  = (ch & 31) << 2;
            cp16(&Bs[st][row * BSTR + cc], Bb + (size_t)(k0 + row) * N + cc);
        }
    };

    issue(0, 0);
    cp_commit();

    for (int t = 0; t < T; t++) {
        cp_wait0();
        __syncthreads();
        if (t + 1 < T) { issue(t + 1, (t + 1) & 1); cp_commit(); }

        const float* as = As[t & 1];
        const float* bs = Bs[t & 1];
        #pragma unroll
        for (int kk = 0; kk < GBK; kk += 8) {
            unsigned a[2][4];
            #pragma unroll
            for (int mt = 0; mt < 2; mt++) {
                const float* qp = as + (wm * 32 + mt * 16 + gq) * ASTR + kk + tig;
                a[mt][0] = fu(qp[0]);
                a[mt][1] = fu(qp[8 * ASTR]);
                a[mt][2] = fu(qp[4]);
                a[mt][3] = fu(qp[8 * ASTR + 4]);
            }
            #pragma unroll
            for (int nt = 0; nt < 8; nt++) {
                int col = wn * 64 + nt * 8 + gq;
                unsigned b0 = fu(bs[(kk + tig)     * BSTR + col]);
                unsigned b1 = fu(bs[(kk + tig + 4) * BSTR + col]);
                mma8(c[0][nt], a[0], b0, b1);
                mma8(c[1][nt], a[1], b0, b1);
            }
        }
    }

    #pragma unroll
    for (int mt = 0; mt < 2; mt++) {
        int row0 = blockIdx.y * GBM + wm * 32 + mt * 16 + gq;
        #pragma unroll
        for (int nt = 0; nt < 8; nt++) {
            int col = blockIdx.x * GBN + wn * 64 + nt * 8 + 2 * tig;
            *(float2*)(C + (size_t)row0 * N + col)       = make_float2(c[mt][nt][0], c[mt][nt][1]);
            *(float2*)(C + (size_t)(row0 + 8) * N + col) = make_float2(c[mt][nt][2], c[mt][nt][3]);
        }
    }
}

// ---------------- fused per-head RMSNorm + RoPE (in-place) ------------------
__global__ __launch_bounds__(128) void norm_rope_kernel(
    float* __restrict__ buf, const float* __restrict__ w,
    const float* __restrict__ cosb, const float* __restrict__ sinb, int nheads)
{
    const int blk  = blockIdx.x;
    const int head = blk % nheads;
    const int bs   = blk / nheads;
    const int s    = bs % S_;
    float* row = buf + ((size_t)bs * nheads + head) * D_;
    const int d = threadIdx.x;

    float v = row[d];
    float ss = v * v;
    #pragma unroll
    for (int o = 16; o > 0; o >>= 1) ss += __shfl_xor_sync(0xffffffffu, ss, o);

    __shared__ float warp_ss[4];
    __shared__ float sh[D_];
    if ((d & 31) == 0) warp_ss[d >> 5] = ss;
    __syncthreads();
    float total = warp_ss[0] + warp_ss[1] + warp_ss[2] + warp_ss[3];
    float r = rsqrtf(total * (1.0f / (float)D_) + EPS_);
    float xn = v * r * w[d];
    sh[d] = xn;
    __syncthreads();
    float rot = (d < 64) ? -sh[d + 64] : sh[d - 64];
    row[d] = xn * cosb[s * D_ + d] + rot * sinb[s * D_ + d];
}

// ---------------- causal GQA flash attention (tf32 tensor cores) -------------
// grid: (16 qblocks, H, B); 256 threads (8 warps); BQ=128, BK=64, D=128
// warp w owns query rows [w*16, w*16+16)
#define BQ 128
#define BKT 64
#define QSTR 132
#define PSTR 68

__global__ __launch_bounds__(256) void flash_tc(
    const float* __restrict__ q, const float* __restrict__ k,
    const float* __restrict__ v, float* __restrict__ o)
{
    extern __shared__ float sm[];
    float* sQ = sm;                       // 128*132
    float* sK = sQ + BQ * QSTR;           // 64*132
    float* sV = sK + BKT * QSTR;          // 64*132
    float* sP = sV + BKT * QSTR;          // 128*68

    const int qb  = (gridDim.x - 1) - blockIdx.x;   // heavy tiles first
    const int h   = blockIdx.y;
    const int b   = blockIdx.z;
    const int kvh = h >> 1;
    const int tid  = threadIdx.x;
    const int lane = tid & 31;
    const int warp = tid >> 5;
    const int gq   = lane >> 2;
    const int tig  = lane & 3;
    const int q0   = qb * BQ;

    // Load + tf32-round Q tile [128][128]
    for (int i = tid; i < BQ * 32; i += 256) {
        int row = i >> 5;
        int cc  = (i & 31) << 2;
        float4 val = *(const float4*)(q + (((size_t)(b * S_ + q0 + row) * H_ + h) * D_) + cc);
        float* p = sQ + row * QSTR + cc;
        p[0] = tf32r(val.x); p[1] = tf32r(val.y); p[2] = tf32r(val.z); p[3] = tf32r(val.w);
    }

    float oc[16][4];
    #pragma unroll
    for (int nt = 0; nt < 16; nt++)
        #pragma unroll
        for (int i = 0; i < 4; i++) oc[nt][i] = 0.0f;
    float mrow0 = -1e30f, mrow1 = -1e30f;
    float lrow0 = 0.0f,   lrow1 = 0.0f;

    const int r0 = q0 + warp * 16 + gq;   // row for c0/c1
    const int r1 = r0 + 8;                // row for c2/c3
    const int jmax = 2 * qb + 1;          // last key tile index

    for (int j = 0; j <= jmax; j++) {
        const int kt0 = j * BKT;
        __syncthreads();  // prior PV reads of sV done before overwrite
        for (int i = tid; i < BKT * 32; i += 256) {
            int row = i >> 5;
            int cc  = (i & 31) << 2;
            size_t base = (((size_t)(b * S_ + kt0 + row) * KV_ + kvh) * D_) + cc;
            float4 kv4 = *(const float4*)(k + base);
            float4 vv4 = *(const float4*)(v + base);
            float* pk = sK + row * QSTR + cc;
            pk[0] = tf32r(kv4.x); pk[1] = tf32r(kv4.y); pk[2] = tf32r(kv4.z); pk[3] = tf32r(kv4.w);
            float* pv = sV + row * QSTR + cc;
            pv[0] = tf32r(vv4.x); pv[1] = tf32r(vv4.y); pv[2] = tf32r(vv4.z); pv[3] = tf32r(vv4.w);
        }
        __syncthreads();

        // S = Q K^T : 8 n-tiles over 64 keys, k-loop over D
        float s[8][4];
        #pragma unroll
        for (int nt = 0; nt < 8; nt++)
            #pragma unroll
            for (int i = 0; i < 4; i++) s[nt][i] = 0.0f;

        #pragma unroll
        for (int kk = 0; kk < D_; kk += 8) {
            unsigned a[4];
            const float* qp = sQ + (warp * 16 + gq) * QSTR + kk + tig;
            a[0] = fu(qp[0]);
            a[1] = fu(qp[8 * QSTR]);
            a[2] = fu(qp[4]);
            a[3] = fu(qp[8 * QSTR + 4]);
            #pragma unroll
            for (int nt = 0; nt < 8; nt++) {
                const float* kp = sK + (nt * 8 + gq) * QSTR + kk + tig;
                unsigned b0 = fu(kp[0]);
                unsigned b1 = fu(kp[4]);
                mma8(s[nt], a, b0, b1);
            }
        }

        // scale + causal mask + row max
        float mx0 = -1e30f, mx1 = -1e30f;
        #pragma unroll
        for (int nt = 0; nt < 8; nt++) {
            int kg = kt0 + nt * 8 + 2 * tig;
            s[nt][0] = (kg     <= r0) ? s[nt][0] * SCALE_ : -1e30f;
            s[nt][1] = (kg + 1 <= r0) ? s[nt][1] * SCALE_ : -1e30f;
            s[nt][2] = (kg     <= r1) ? s[nt][2] * SCALE_ : -1e30f;
            s[nt][3] = (kg + 1 <= r1) ? s[nt][3] * SCALE_ : -1e30f;
            mx0 = fmaxf(mx0, fmaxf(s[nt][0], s[nt][1]));
            mx1 = fmaxf(mx1, fmaxf(s[nt][2], s[nt][3]));
        }
        mx0 = fmaxf(mx0, __shfl_xor_sync(0xffffffffu, mx0, 1));
        mx0 = fmaxf(mx0, __shfl_xor_sync(0xffffffffu, mx0, 2));
        mx1 = fmaxf(mx1, __shfl_xor_sync(0xffffffffu, mx1, 1));
        mx1 = fmaxf(mx1, __shfl_xor_sync(0xffffffffu, mx1, 2));

        float mn0 = fmaxf(mrow0, mx0), mn1 = fmaxf(mrow1, mx1);
        float al0 = __expf(mrow0 - mn0), al1 = __expf(mrow1 - mn1);

        float ls0 = 0.0f, ls1 = 0.0f;
        float* pbase = sP + (warp * 16 + gq) * PSTR + 2 * tig;
        #pragma unroll
        for (int nt = 0; nt < 8; nt++) {
            float p0 = __expf(s[nt][0] - mn0);
            float p1 = __expf(s[nt][1] - mn0);
            float p2 = __expf(s[nt][2] - mn1);
            float p3 = __expf(s[nt][3] - mn1);
            ls0 += p0 + p1;
            ls1 += p2 + p3;
            pbase[nt * 8]                = tf32r(p0);
            pbase[nt * 8 + 1]            = tf32r(p1);
            pbase[nt * 8 + 8 * PSTR]     = tf32r(p2);
            pbase[nt * 8 + 8 * PSTR + 1] = tf32r(p3);
        }
        ls0 += __shfl_xor_sync(0xffffffffu, ls0, 1);
        ls0 += __shfl_xor_sync(0xffffffffu, ls0, 2);
        ls1 += __shfl_xor_sync(0xffffffffu, ls1, 1);
        ls1 += __shfl_xor_sync(0xffffffffu, ls1, 2);
        lrow0 = lrow0 * al0 + ls0;  mrow0 = mn0;
        lrow1 = lrow1 * al1 + ls1;  mrow1 = mn1;

        // rescale O accumulators
        #pragma unroll
        for (int nt = 0; nt < 16; nt++) {
            oc[nt][0] *= al0; oc[nt][1] *= al0;
            oc[nt][2] *= al1; oc[nt][3] *= al1;
        }
        __syncwarp();

        // O += P V : 16 n-tiles over D, k-loop over 64 keys
        #pragma unroll
        for (int kt = 0; kt < BKT; kt += 8) {
            unsigned a[4];
            const float* pp = sP + (warp * 16 + gq) * PSTR + kt + tig;
            a[0] = fu(pp[0]);
            a[1] = fu(pp[8 * PSTR]);
            a[2] = fu(pp[4]);
            a[3] = fu(pp[8 * PSTR + 4]);
            #pragma unroll
            for (int nt = 0; nt < 16; nt++) {
                const float* vp = sV + (kt + tig) * QSTR + nt * 8 + gq;
                unsigned b0 = fu(vp[0]);
                unsigned b1 = fu(vp[4 * QSTR]);
                mma8(oc[nt], a, b0, b1);
            }
        }
        __syncwarp();
    }

    // normalize + tf32-round + write (feeds Wo GEMM directly)
    float inv0 = 1.0f / lrow0, inv1 = 1.0f / lrow1;
    #pragma unroll
    for (int nt = 0; nt < 16; nt++) {
        int col = nt * 8 + 2 * tig;
        float* op0 = o + (((size_t)(b * S_ + r0) * H_ + h) * D_) + col;
        float* op1 = o + (((size_t)(b * S_ + r1) * H_ + h) * D_) + col;
        *(float2*)op0 = make_float2(tf32r(oc[nt][0] * inv0), tf32r(oc[nt][1] * inv0));
        *(float2*)op1 = make_float2(tf32r(oc[nt][2] * inv1), tf32r(oc[nt][3] * inv1));
    }
}

// ---------------- launch -----------------------------------------------------
extern "C" void kernel_launch(void* const* d_in, const int* in_sizes, int n_in,
                              void* d_out, int out_size)
{
    const float* x    = (const float*)d_in[0];
    const float* Wq   = (const float*)d_in[1];
    const float* Wk   = (const float*)d_in[2];
    const float* Wv   = (const float*)d_in[3];
    const float* Wo   = (const float*)d_in[4];
    const float* qw   = (const float*)d_in[5];
    const float* kw   = (const float*)d_in[6];
    const float* cosb = (const float*)d_in[7];
    const float* sinb = (const float*)d_in[8];

    float *qb, *kb, *vb, *ob, *xr, *wqr, *wkr, *wvr, *wor;
    cudaGetSymbolAddress((void**)&qb, g_q);
    cudaGetSymbolAddress((void**)&kb, g_k);
    cudaGetSymbolAddress((void**)&vb, g_v);
    cudaGetSymbolAddress((void**)&ob, g_o);
    cudaGetSymbolAddress((void**)&xr, g_xr);
    cudaGetSymbolAddress((void**)&wqr, g_wqr);
    cudaGetSymbolAddress((void**)&wkr, g_wkr);
    cudaGetSymbolAddress((void**)&wvr, g_wvr);
    cudaGetSymbolAddress((void**)&wor, g_wor);

    const int M = B_ * S_;  // 4096

    // pre-round GEMM inputs to tf32 (numerics identical to in-kernel cvt)
    {
        int n4;
        n4 = (B_ * S_ * HID_) / 4;
        round_tf32_kernel<<<(n4 + 255) / 256, 256>>>(x, xr, n4);
        n4 = (HID_ * H_ * D_) / 4;
        round_tf32_kernel<<<(n4 + 255) / 256, 256>>>(Wq, wqr, n4);
        n4 = (HID_ * KV_ * D_) / 4;
        round_tf32_kernel<<<(n4 + 255) / 256, 256>>>(Wk, wkr, n4);
        round_tf32_kernel<<<(n4 + 255) / 256, 256>>>(Wv, wvr, n4);
        n4 = (H_ * D_ * HID_) / 4;
        round_tf32_kernel<<<(n4 + 255) / 256, 256>>>(Wo, wor, n4);
    }

    // QKV projections (cp.async tf32 tensor cores)
    tf32_gemm_async<<<dim3((H_ * D_) / GBN, M / GBM), 256>>>(xr, wqr, qb, M, H_ * D_, HID_);
    tf32_gemm_async<<<dim3((KV_ * D_) / GBN, M / GBM), 256>>>(xr, wkr, kb, M, KV_ * D_, HID_);
    tf32_gemm_async<<<dim3((KV_ * D_) / GBN, M / GBM), 256>>>(xr, wvr, vb, M, KV_ * D_, HID_);

    // RMSNorm + RoPE (in place)
    norm_rope_kernel<<<B_ * S_ * H_, 128>>>(qb, qw, cosb, sinb, H_);
    norm_rope_kernel<<<B_ * S_ * KV_, 128>>>(kb, kw, cosb, sinb, KV_);

    // causal GQA flash attention (tf32 tensor cores, BQ=128, 8 warps)
    const int smem = (BQ * QSTR + 2 * BKT * QSTR + BQ * PSTR) * (int)sizeof(float);  // 169984
    cudaFuncSetAttribute(flash_tc, cudaFuncAttributeMaxDynamicSharedMemorySize, smem);
    flash_tc<<<dim3(S_ / BQ, H_, B_), 256, smem>>>(qb, kb, vb, ob);

    // output projection -> d_out
    tf32_gemm_async<<<dim3(HID_ / GBN, M / GBM), 256>>>(ob, wor, (float*)d_out, M, HID_, HID_);
}